// round 14
// baseline (speedup 1.0000x reference)
#include <cuda_runtime.h>
#include <cuda_fp16.h>
#include <math.h>

#define BB 16384
#define NN 20
#define DD 128
#define HH 4
#define SCALE 0.1020620726159658f /* 1/sqrt(96) */

// ---------------- device scratch ----------------
__device__ __half g_qt[(size_t)BB * 1536];   // q-tilde (fp16)
__device__ __half g_c [(size_t)BB * 1536];   // context (fp16)
__device__ __half g_ao[(size_t)BB * 384];    // attn out pre-fc (fp16)
__device__ __half g_preh[(size_t)BB * 384];  // fc+bias+residual (fp16, pre-LN)
__device__ float  g_s1[4 * BB];              // per-(cq,row) LN partial sums
__device__ float  g_s2[4 * BB];
__device__ __half g_Mqk[1536 * 256];         // fused Wq*Wk matrix [j][k] (fp16)

// ---------------- prep: M_qk[j][k] = sum_d Wq[h*96+d][keff] * Wk[h*96+d][jj] ----------------
__global__ void __launch_bounds__(256) k_prepm(const float* __restrict__ Wq,
                                               const float* __restrict__ Wk) {
    __shared__ float wk[8 * 96];
    const int tid = threadIdx.x;
    const int j0 = blockIdx.x * 8;
    const int h = j0 / 384;
    const int jj0 = j0 - h * 384;

    for (int i = tid; i < 768; i += 256) {
        int jo = i / 96, d = i - jo * 96;
        wk[jo * 96 + d] = Wk[(size_t)(h * 96 + d) * 384 + jj0 + jo];
    }
    __syncthreads();

    const int k = tid;
    const int keff = (k < 128) ? k : k + 128;
    float acc[8] = {};
    for (int d = 0; d < 96; ++d) {
        float wq = __ldg(&Wq[(size_t)(h * 96 + d) * 384 + keff]);
        #pragma unroll
        for (int jo = 0; jo < 8; ++jo)
            acc[jo] = fmaf(wq, wk[jo * 96 + d], acc[jo]);
    }
    #pragma unroll
    for (int jo = 0; jo < 8; ++jo)
        g_Mqk[(size_t)(j0 + jo) * 256 + k] = __float2half_rn(acc[jo]);
}

// ---------- fp16 mma m16n8k16 ----------
__device__ __forceinline__ void mma16(float* c, unsigned a0, unsigned a1, unsigned a2,
                                      unsigned a3, unsigned b0, unsigned b1) {
    asm volatile(
        "mma.sync.aligned.m16n8k16.row.col.f32.f16.f16.f32 "
        "{%0,%1,%2,%3}, {%4,%5,%6,%7}, {%8,%9}, {%0,%1,%2,%3};"
        : "+f"(c[0]), "+f"(c[1]), "+f"(c[2]), "+f"(c[3])
        : "r"(a0), "r"(a1), "r"(a2), "r"(a3), "r"(b0), "r"(b1));
}

template<int NT>
__device__ __forceinline__ void mma16_warp2(float* acc, const __half* sa, const __half* sbt,
                                            int lane) {
    const int grp = lane >> 2, tig = lane & 3;
    #pragma unroll
    for (int ks = 0; ks < 2; ++ks) {
        const __half* ap0 = sa + grp * 40 + ks * 16 + tig * 2;
        const __half* ap1 = ap0 + 16 * 40;
        unsigned a00 = *(const unsigned*)ap0;
        unsigned a01 = *(const unsigned*)(ap0 + 320);
        unsigned a02 = *(const unsigned*)(ap0 + 8);
        unsigned a03 = *(const unsigned*)(ap0 + 328);
        unsigned a10 = *(const unsigned*)ap1;
        unsigned a11 = *(const unsigned*)(ap1 + 320);
        unsigned a12 = *(const unsigned*)(ap1 + 8);
        unsigned a13 = *(const unsigned*)(ap1 + 328);
        #pragma unroll
        for (int nt = 0; nt < NT; ++nt) {
            const __half* bp = sbt + (nt * 8 + grp) * 40 + ks * 16 + tig * 2;
            unsigned b0 = *(const unsigned*)bp;
            unsigned b1 = *(const unsigned*)(bp + 8);
            mma16(acc + nt * 4, a00, a01, a02, a03, b0, b1);
            mma16(acc + (NT + nt) * 4, a10, a11, a12, a13, b0, b1);
        }
    }
}

template<int NT>
__device__ __forceinline__ void mma16_warp(float* acc, const __half* sa, const __half* sbt,
                                           int lane) {
    const int grp = lane >> 2, tig = lane & 3;
    #pragma unroll
    for (int ks = 0; ks < 2; ++ks) {
        const __half* ap0 = sa + grp * 40 + ks * 16 + tig * 2;
        unsigned a00 = *(const unsigned*)ap0;
        unsigned a01 = *(const unsigned*)(ap0 + 320);
        unsigned a02 = *(const unsigned*)(ap0 + 8);
        unsigned a03 = *(const unsigned*)(ap0 + 328);
        #pragma unroll
        for (int nt = 0; nt < NT; ++nt) {
            const __half* bp = sbt + (nt * 8 + grp) * 40 + ks * 16 + tig * 2;
            unsigned b0 = *(const unsigned*)bp;
            unsigned b1 = *(const unsigned*)(bp + 8);
            mma16(acc + nt * 4, a00, a01, a02, a03, b0, b1);
        }
    }
}

#define LOADB(W, COLB, KS, KT)                                                \
    _Pragma("unroll")                                                         \
    for (int jj = 0; jj < 3; ++jj) {                                          \
        int qidx = tid + 256 * jj, col = qidx >> 3, q = qidx & 7;             \
        breg[jj] = *(const float4*)&(W)[(size_t)((COLB) + col) * (KS) + (KT) + q * 4]; \
    }
#define STSB()                                                                \
    _Pragma("unroll")                                                         \
    for (int jj = 0; jj < 3; ++jj) {                                          \
        int qidx = tid + 256 * jj, col = qidx >> 3, q = qidx & 7;             \
        float4 v = breg[jj];                                                  \
        *(__half2*)&sbt[col * 40 + q * 4]     = __floats2half2_rn(v.x, v.y);  \
        *(__half2*)&sbt[col * 40 + q * 4 + 2] = __floats2half2_rn(v.z, v.w);  \
    }
#define LOADA_H(SRC, RSTRIDE, ROWB, KT)                                       \
    _Pragma("unroll")                                                         \
    for (int j = 0; j < 8; ++j)                                               \
        aregu[j] = *(const unsigned*)&(SRC)[(size_t)((ROWB) + rowb + 16 * j) * (RSTRIDE) + (KT) + 2 * kp];
#define STSA_H()                                                              \
    _Pragma("unroll")                                                         \
    for (int j = 0; j < 8; ++j)                                               \
        *(unsigned*)&saf[(rowb + 16 * j) * 40 + 2 * kp] = aregu[j];

// ---------------- k_qt: g_qt[B x 1536] = A_eff[B x 256] @ M_qk^T ----------------
__global__ void __launch_bounds__(256, 2) k_qt(const float* __restrict__ src,
                                               const float* __restrict__ src_ts,
                                               const float* __restrict__ freq,
                                               const float* __restrict__ phase) {
    __shared__ __align__(16) __half saf[128 * 40];
    __shared__ __align__(16) __half sbt[96 * 40];
    __shared__ float sts[128];
    const int tid = threadIdx.x, lane = tid & 31, wid = tid >> 5;
    const int bt = blockIdx.x >> 4, cq = blockIdx.x & 15;
    const int b0 = bt * 128, c0 = cq * 96;
    const int kk = tid & 31, row0 = tid >> 5;
    const int rslab = (wid >> 1) * 32, chalf = (wid & 1) * 48;

    if (tid < 128) sts[tid] = src_ts[b0 + tid];
    __syncthreads();

    float areg[16]; uint2 bregu[3];
    #define LOADA_QT(KT) do {                                                 \
        int m = (KT) + kk;                                                    \
        if (m < 128) {                                                        \
            _Pragma("unroll")                                                 \
            for (int j = 0; j < 16; ++j)                                      \
                areg[j] = src[(size_t)(b0 + row0 + 8 * j) * 128 + m];         \
        } else {                                                              \
            float f = freq[m - 128], ph = phase[m - 128];                     \
            _Pragma("unroll")                                                 \
            for (int j = 0; j < 16; ++j)                                      \
                areg[j] = __cosf(sts[row0 + 8 * j] * f + ph);                 \
        } } while (0)
    #define LOADB_QT(KT)                                                      \
        _Pragma("unroll")                                                     \
        for (int jj = 0; jj < 3; ++jj) {                                      \
            int qidx = tid + 256 * jj, col = qidx >> 3, q = qidx & 7;         \
            bregu[jj] = *(const uint2*)&g_Mqk[(size_t)(c0 + col) * 256 + (KT) + q * 4]; \
        }
    #define STSA_QT()                                                         \
        _Pragma("unroll")                                                     \
        for (int j = 0; j < 16; ++j)                                          \
            saf[(row0 + 8 * j) * 40 + kk] = __float2half_rn(areg[j]);
    #define STSB_QT()                                                         \
        _Pragma("unroll")                                                     \
        for (int jj = 0; jj < 3; ++jj) {                                      \
            int qidx = tid + 256 * jj, col = qidx >> 3, q = qidx & 7;         \
            *(uint2*)&sbt[col * 40 + q * 4] = bregu[jj];                      \
        }

    LOADA_QT(0); LOADB_QT(0);
    float acc[48] = {};
    for (int t = 0; t < 8; ++t) {
        __syncthreads();
        STSA_QT(); STSB_QT();
        __syncthreads();
        if (t < 7) { LOADA_QT((t + 1) * 32); LOADB_QT((t + 1) * 32); }
        mma16_warp2<6>(acc, saf + rslab * 40, sbt + chalf * 40, lane);
    }
    const int grp = lane >> 2, tig = lane & 3;
    const int r0 = b0 + rslab + grp;
    #pragma unroll
    for (int nt = 0; nt < 6; ++nt) {
        int j = c0 + chalf + nt * 8 + tig * 2;
        *(__half2*)&g_qt[(size_t)r0 * 1536 + j]        = __floats2half2_rn(acc[nt*4+0], acc[nt*4+1]);
        *(__half2*)&g_qt[(size_t)(r0 + 8) * 1536 + j]  = __floats2half2_rn(acc[nt*4+2], acc[nt*4+3]);
        *(__half2*)&g_qt[(size_t)(r0 + 16) * 1536 + j] = __floats2half2_rn(acc[(6+nt)*4+0], acc[(6+nt)*4+1]);
        *(__half2*)&g_qt[(size_t)(r0 + 24) * 1536 + j] = __floats2half2_rn(acc[(6+nt)*4+2], acc[(6+nt)*4+3]);
    }
    #undef LOADA_QT
    #undef LOADB_QT
    #undef STSA_QT
    #undef STSB_QT
}

// ---------------- attention core: one block per batch, batched loads + fp16 smem ----------------
__global__ void __launch_bounds__(256) k_attn(const float* __restrict__ seq,
                                              const float* __restrict__ seq_e,
                                              const float* __restrict__ seq_ts,
                                              const unsigned int* __restrict__ mask,
                                              const float* __restrict__ freq,
                                              const float* __restrict__ phase,
                                              float* __restrict__ attn_out) {
    __shared__ __align__(16) __half kin[NN * 384];   // 15360 B
    __shared__ __align__(16) __half qts[1536];       // 3072 B
    __shared__ float sc[HH][NN];
    __shared__ float pp[HH][NN];
    const int b = blockIdx.x;
    const int tid = threadIdx.x;
    const int w = tid >> 5, lane = tid & 31;

    // --- batched global loads: issue everything before any smem stores ---
    const float4* seq4   = (const float4*)seq;
    const float4* seq_e4 = (const float4*)seq_e;
    const size_t b640 = (size_t)b * 640;
    const bool v2 = (tid < 128);
    float4 sa0 = seq4[b640 + tid];
    float4 sa1 = seq4[b640 + tid + 256];
    float4 se0 = seq_e4[b640 + tid];
    float4 se1 = seq_e4[b640 + tid + 256];
    float4 sa2, se2;
    if (v2) { sa2 = seq4[b640 + tid + 512]; se2 = seq_e4[b640 + tid + 512]; }
    uint4 qv;
    if (tid < 192) qv = ((const uint4*)(g_qt + (size_t)b * 1536))[tid];

    // --- independent MUFU work while loads are in flight ---
    for (int idx = tid; idx < NN * 128; idx += 256) {
        int n = idx >> 7, d = idx & 127;
        kin[n * 384 + 256 + d] = __float2half_rn(__cosf(seq_ts[b * NN + n] * freq[d] + phase[d]));
    }

    // --- store loaded data ---
    #define STK(IDX, A, E) do {                                              \
        int n_ = (IDX) >> 5, q_ = (IDX) & 31;                                \
        *(__half2*)&kin[n_ * 384 + q_ * 4]           = __floats2half2_rn((A).x, (A).y); \
        *(__half2*)&kin[n_ * 384 + q_ * 4 + 2]       = __floats2half2_rn((A).z, (A).w); \
        *(__half2*)&kin[n_ * 384 + 128 + q_ * 4]     = __floats2half2_rn((E).x, (E).y); \
        *(__half2*)&kin[n_ * 384 + 128 + q_ * 4 + 2] = __floats2half2_rn((E).z, (E).w); \
    } while (0)
    STK(tid, sa0, se0);
    STK(tid + 256, sa1, se1);
    if (v2) STK(tid + 512, sa2, se2);
    if (tid < 192) *(uint4*)&qts[tid * 8] = qv;
    #undef STK
    __syncthreads();

    const __half2* kin2 = (const __half2*)kin;
    const __half2* qts2 = (const __half2*)qts;

    for (int p = w; p < HH * NN; p += 8) {
        int h = p / NN, n = p - h * NN;
        float partial = 0.f;
        #pragma unroll
        for (int t = 0; t < 6; ++t) {
            int e = lane + 32 * t;
            float2 qf = __half22float2(qts2[h * 192 + e]);
            float2 kf = __half22float2(kin2[n * 192 + e]);
            partial = fmaf(qf.x, kf.x, partial);
            partial = fmaf(qf.y, kf.y, partial);
        }
        #pragma unroll
        for (int off = 16; off; off >>= 1)
            partial += __shfl_xor_sync(0xffffffffu, partial, off);
        if (lane == 0) {
            float s = partial * SCALE;
            if (mask[b * NN + n] != 0u) s = -1.0e10f;
            sc[h][n] = s;
        }
    }
    __syncthreads();

    if (w < HH) {
        float v = (lane < NN) ? sc[w][lane] : -3.0e38f;
        float mx = v;
        #pragma unroll
        for (int off = 16; off; off >>= 1)
            mx = fmaxf(mx, __shfl_xor_sync(0xffffffffu, mx, off));
        float e = (lane < NN) ? expf(v - mx) : 0.f;
        float s = e;
        #pragma unroll
        for (int off = 16; off; off >>= 1)
            s += __shfl_xor_sync(0xffffffffu, s, off);
        float prob = e / s;
        if (lane < NN) {
            pp[w][lane] = prob;
            attn_out[((size_t)w * BB + b) * NN + lane] = prob;
        }
    }
    __syncthreads();

    __half2* gc2 = (__half2*)(g_c + (size_t)b * 1536);
    for (int idx = tid; idx < 768; idx += 256) {
        int h = idx / 192, e = idx - h * 192;
        float sx = 0.f, sy = 0.f;
        #pragma unroll
        for (int n = 0; n < NN; ++n) {
            float2 kf = __half22float2(kin2[n * 192 + e]);
            float pr = pp[h][n];
            sx = fmaf(pr, kf.x, sx);
            sy = fmaf(pr, kf.y, sy);
        }
        gc2[idx] = __floats2half2_rn(sx, sy);
    }
}

// ---------------- k_vout: g_ao head slab = g_c_h[B x 384] @ Wv_h^T ----------------
__global__ void __launch_bounds__(256, 2) k_vout(const float* __restrict__ Wv) {
    __shared__ __align__(16) __half saf[128 * 40];
    __shared__ __align__(16) __half sbt[96 * 40];
    const int tid = threadIdx.x, lane = tid & 31, wid = tid >> 5;
    const int bt = blockIdx.x >> 2, h = blockIdx.x & 3;
    const int b0 = bt * 128;
    const int rowb = tid >> 4, kp = tid & 15;
    const int rslab = (wid >> 1) * 32, chalf = (wid & 1) * 48;

    unsigned aregu[8]; float4 breg[3];
    LOADA_H(g_c, 1536, b0, h * 384 + 0); LOADB(Wv, h * 96, 384, 0);
    float acc[48] = {};
    for (int t = 0; t < 12; ++t) {
        __syncthreads();
        STSA_H(); STSB();
        __syncthreads();
        if (t < 11) {
            LOADA_H(g_c, 1536, b0, h * 384 + (t + 1) * 32);
            LOADB(Wv, h * 96, 384, (t + 1) * 32);
        }
        mma16_warp2<6>(acc, saf + rslab * 40, sbt + chalf * 40, lane);
    }
    const int grp = lane >> 2, tig = lane & 3;
    const int r0 = b0 + rslab + grp;
    #pragma unroll
    for (int nt = 0; nt < 6; ++nt) {
        int col = h * 96 + chalf + nt * 8 + tig * 2;
        *(__half2*)&g_ao[(size_t)r0 * 384 + col]        = __floats2half2_rn(acc[nt*4+0], acc[nt*4+1]);
        *(__half2*)&g_ao[(size_t)(r0 + 8) * 384 + col]  = __floats2half2_rn(acc[nt*4+2], acc[nt*4+3]);
        *(__half2*)&g_ao[(size_t)(r0 + 16) * 384 + col] = __floats2half2_rn(acc[(6+nt)*4+0], acc[(6+nt)*4+1]);
        *(__half2*)&g_ao[(size_t)(r0 + 24) * 384 + col] = __floats2half2_rn(acc[(6+nt)*4+2], acc[(6+nt)*4+3]);
    }
}

// ---------------- k_fc: g_preh = fp16(g_ao @ fc_w^T + b + residual), + LN partial sums ----------------
__global__ void __launch_bounds__(256, 2) k_fc(const float* __restrict__ src,
                                               const float* __restrict__ src_ts,
                                               const float* __restrict__ freq,
                                               const float* __restrict__ phase,
                                               const float* __restrict__ fc_w,
                                               const float* __restrict__ fc_b) {
    __shared__ __align__(16) __half saf[128 * 40];
    __shared__ __align__(16) __half sbt[96 * 40];
    __shared__ float ps1[8][32];
    __shared__ float ps2[8][32];
    const int tid = threadIdx.x, lane = tid & 31, wid = tid >> 5;
    const int bt = blockIdx.x >> 2, cq = blockIdx.x & 3;
    const int b0 = bt * 128, c0 = cq * 96;
    const int rowb = tid >> 4, kp = tid & 15;
    const int rslab = (wid >> 1) * 32, chalf = (wid & 1) * 48;

    unsigned aregu[8]; float4 breg[3];
    LOADA_H(g_ao, 384, b0, 0); LOADB(fc_w, c0, 384, 0);
    float acc[48] = {};
    for (int t = 0; t < 12; ++t) {
        __syncthreads();
        STSA_H(); STSB();
        __syncthreads();
        if (t < 11) {
            LOADA_H(g_ao, 384, b0, (t + 1) * 32);
            LOADB(fc_w, c0, 384, (t + 1) * 32);
        }
        mma16_warp2<6>(acc, saf + rslab * 40, sbt + chalf * 40, lane);
    }
    const int grp = lane >> 2, tig = lane & 3;
    const int r0 = b0 + rslab + grp;
    float tsv[4];
    #pragma unroll
    for (int s = 0; s < 4; ++s) tsv[s] = src_ts[r0 + 8 * s];

    float s1l[4] = {}, s2l[4] = {};
    #pragma unroll
    for (int s = 0; s < 4; ++s) {
        const int rr = r0 + 8 * s;
        const int ab = (s >> 1) * 24 + (s & 1) * 2;
        #pragma unroll
        for (int nt = 0; nt < 6; ++nt) {
            int col = c0 + chalf + nt * 8 + tig * 2;
            float v0 = acc[ab + nt * 4 + 0] + fc_b[col];
            float v1 = acc[ab + nt * 4 + 1] + fc_b[col + 1];
            if (col < 128) {
                v0 += src[(size_t)rr * 128 + col];
                v1 += src[(size_t)rr * 128 + col + 1];
            } else if (col >= 256) {
                int d = col - 256;
                v0 += __cosf(tsv[s] * freq[d] + phase[d]);
                v1 += __cosf(tsv[s] * freq[d + 1] + phase[d + 1]);
            }
            *(__half2*)&g_preh[(size_t)rr * 384 + col] = __floats2half2_rn(v0, v1);
            s1l[s] += v0 + v1;
            s2l[s] = fmaf(v0, v0, fmaf(v1, v1, s2l[s]));
        }
    }
    // quad-reduce over tig (lanes grp*4+tig share rows)
    #pragma unroll
    for (int s = 0; s < 4; ++s) {
        #pragma unroll
        for (int off = 1; off <= 2; off <<= 1) {
            s1l[s] += __shfl_xor_sync(0xffffffffu, s1l[s], off);
            s2l[s] += __shfl_xor_sync(0xffffffffu, s2l[s], off);
        }
    }
    if (tig == 0) {
        #pragma unroll
        for (int s = 0; s < 4; ++s) {
            ps1[wid][grp + 8 * s] = s1l[s];
            ps2[wid][grp + 8 * s] = s2l[s];
        }
    }
    __syncthreads();
    if (tid < 128) {
        int g = tid >> 5, lr = tid & 31;
        g_s1[cq * BB + b0 + tid] = ps1[2 * g][lr] + ps1[2 * g + 1][lr];
        g_s2[cq * BB + b0 + tid] = ps2[2 * g][lr] + ps2[2 * g + 1][lr];
    }
}

// ---------------- k_mlp: LN-on-load + fp16 tensor-core MLP, 64 rows/block ----------------
__global__ void __launch_bounds__(256) k_mlp(const float* __restrict__ src,
                                             const float* __restrict__ ln_g,
                                             const float* __restrict__ ln_b,
                                             const float* __restrict__ m1_w,
                                             const float* __restrict__ m1_b,
                                             const float* __restrict__ m2_w,
                                             const float* __restrict__ m2_b,
                                             float* __restrict__ y) {
    __shared__ __align__(16) __half saf[64 * 40];
    __shared__ __align__(16) __half sbtm[128 * 40];
    __shared__ __align__(16) __half hst[4 * 64 * 40];
    __shared__ float smu[64], sinv[64];
    const int tid = threadIdx.x, lane = tid & 31, wid = tid >> 5;
    const int b0 = blockIdx.x * 64;
    const int rowb = tid >> 4, kp = tid & 15;

    // LN stats from precomputed partials
    if (tid < 64) {
        int row = b0 + tid;
        float s1 = g_s1[row] + g_s1[BB + row] + g_s1[2 * BB + row] + g_s1[3 * BB + row];
        float s2 = g_s2[row] + g_s2[BB + row] + g_s2[2 * BB + row] + g_s2[3 * BB + row];
        float mu = s1 * (1.f / 384.f);
        float var = s2 * (1.f / 384.f) - mu * mu;
        smu[tid] = mu;
        sinv[tid] = rsqrtf(var + 1e-5f);
    }
    __syncthreads();

    float2 areg2[4]; float4 breg4[4];
    #define LOADB4(W, KS, KT)                                                  \
        _Pragma("unroll")                                                      \
        for (int jj = 0; jj < 4; ++jj) {                                       \
            int qidx = tid + 256 * jj, col = qidx >> 3, q = qidx & 7;          \
            breg4[jj] = *(const float4*)&(W)[(size_t)col * (KS) + (KT) + q * 4]; \
        }
    #define STSB4()                                                            \
        _Pragma("unroll")                                                      \
        for (int jj = 0; jj < 4; ++jj) {                                       \
            int qidx = tid + 256 * jj, col = qidx >> 3, q = qidx & 7;          \
            float4 v = breg4[jj];                                              \
            *(__half2*)&sbtm[col * 40 + q * 4]     = __floats2half2_rn(v.x, v.y); \
            *(__half2*)&sbtm[col * 40 + q * 4 + 2] = __floats2half2_rn(v.z, v.w); \
        }
    #define LOADA_X(KT) do {                                                   \
        if ((KT) < 384) {                                                      \
            _Pragma("unroll")                                                  \
            for (int j = 0; j < 4; ++j) {                                      \
                __half2 hv = *(const __half2*)&g_preh[(size_t)(b0 + rowb + 16 * j) * 384 + (KT) + 2 * kp]; \
                areg2[j] = __half22float2(hv);                                  \
            }                                                                   \
        } else {                                                                \
            _Pragma("unroll")                                                  \
            for (int j = 0; j < 4; ++j)                                        \
                areg2[j] = *(const float2*)&src[(size_t)(b0 + rowb + 16 * j) * 128 + (KT) - 384 + 2 * kp]; \
        } } while (0)
    #define STSA_X(KT) do {                                                    \
        if ((KT) < 384) {                                                      \
            int k_ = (KT) + 2 * kp;                                            \
            float lg0 = ln_g[k_], lb0 = ln_b[k_];                              \
            float lg1 = ln_g[k_ + 1], lb1 = ln_b[k_ + 1];                      \
            _Pragma("unroll")                                                  \
            for (int j = 0; j < 4; ++j) {                                      \
                int row = rowb + 16 * j;                                       \
                float x0 = (areg2[j].x - smu[row]) * sinv[row] * lg0 + lb0;    \
                float x1 = (areg2[j].y - smu[row]) * sinv[row] * lg1 + lb1;    \
                *(__half2*)&saf[row * 40 + 2 * kp] = __floats2half2_rn(x0, x1); \
            }                                                                   \
        } else {                                                                \
            _Pragma("unroll")                                                  \
            for (int j = 0; j < 4; ++j)                                        \
                *(__half2*)&saf[(rowb + 16 * j) * 40 + 2 * kp] =               \
                    __floats2half2_rn(areg2[j].x, areg2[j].y);                 \
        } } while (0)

    const int grp = lane >> 2, tig = lane & 3;
    const int rslab = (wid >> 1) * 16, chalf = (wid & 1) * 64;
    const int r0 = rslab + grp;

    LOADA_X(0); LOADB4(m1_w, 512, 0);
    float acc[32] = {};
    for (int t = 0; t < 16; ++t) {
        __syncthreads();
        STSA_X(t * 32); STSB4();
        __syncthreads();
        if (t < 15) { LOADA_X((t + 1) * 32); LOADB4(m1_w, 512, (t + 1) * 32); }
        mma16_warp<8>(acc, saf + rslab * 40, sbtm + chalf * 40, lane);
    }
    #pragma unroll
    for (int nt = 0; nt < 8; ++nt) {
        int col = chalf + nt * 8 + tig * 2;
        float b1a = m1_b[col], b1b = m1_b[col + 1];
        __half* hb = hst + (col >> 5) * 2560 + (col & 31);
        *(__half2*)&hb[r0 * 40] =
            __floats2half2_rn(fmaxf(acc[nt*4+0] + b1a, 0.f), fmaxf(acc[nt*4+1] + b1b, 0.f));
        *(__half2*)&hb[(r0 + 8) * 40] =
            __floats2half2_rn(fmaxf(acc[nt*4+2] + b1a, 0.f), fmaxf(acc[nt*4+3] + b1b, 0.f));
    }
    #pragma unroll
    for (int i = 0; i < 32; ++i) acc[i] = 0.f;

    for (int t = 0; t < 4; ++t) {
        LOADB4(m2_w, 128, t * 32);
        __syncthreads();
        STSB4();
        __syncthreads();
        mma16_warp<8>(acc, hst + t * 2560 + rslab * 40, sbtm + chalf * 40, lane);
    }
    #pragma unroll
    for (int nt = 0; nt < 8; ++nt) {
        int col = chalf + nt * 8 + tig * 2;
        float b2a = m2_b[col], b2b = m2_b[col + 1];
        *(float2*)&y[(size_t)(b0 + r0) * 128 + col] =
            make_float2(acc[nt*4+0] + b2a, acc[nt*4+1] + b2b);
        *(float2*)&y[(size_t)(b0 + r0 + 8) * 128 + col] =
            make_float2(acc[nt*4+2] + b2a, acc[nt*4+3] + b2b);
    }
    #undef LOADB4
    #undef STSB4
    #undef LOADA_X
    #undef STSA_X
}

// ---------------- launch ----------------
extern "C" void kernel_launch(void* const* d_in, const int* in_sizes, int n_in,
                              void* d_out, int out_size) {
    const float* src    = (const float*)d_in[0];
    const float* seq    = (const float*)d_in[1];
    const float* seq_e  = (const float*)d_in[2];
    const float* src_ts = (const float*)d_in[3];
    const float* seq_ts = (const float*)d_in[4];
    const unsigned int* mask = (const unsigned int*)d_in[5];
    const float* freq   = (const float*)d_in[6];
    const float* phase  = (const float*)d_in[7];
    const float* Wq     = (const float*)d_in[8];
    const float* Wk     = (const float*)d_in[9];
    const float* Wv     = (const float*)d_in[10];
    const float* fc_w   = (const float*)d_in[11];
    const float* fc_b   = (const float*)d_in[12];
    const float* ln_g   = (const float*)d_in[13];
    const float* ln_b   = (const float*)d_in[14];
    const float* m1_w   = (const float*)d_in[15];
    const float* m1_b   = (const float*)d_in[16];
    const float* m2_w   = (const float*)d_in[17];
    const float* m2_b   = (const float*)d_in[18];

    float* y_out = (float*)d_out;
    float* attn_out = y_out + (size_t)BB * DD;

    k_prepm <<<192, 256>>>(Wq, Wk);
    k_qt    <<<2048, 256>>>(src, src_ts, freq, phase);
    k_attn  <<<BB, 256>>>(seq, seq_e, seq_ts, mask, freq, phase, attn_out);
    k_vout  <<<512, 256>>>(Wv);
    k_fc    <<<512, 256>>>(src, src_ts, freq, phase, fc_w, fc_b);
    k_mlp   <<<256, 256>>>(src, ln_g, ln_b, m1_w, m1_b, m2_w, m2_b, y_out);
}

// round 15
// speedup vs baseline: 1.0143x; 1.0143x over previous
#include <cuda_runtime.h>
#include <cuda_fp16.h>
#include <math.h>

#define BB 16384
#define NN 20
#define DD 128
#define HH 4
#define SCALE 0.1020620726159658f /* 1/sqrt(96) */

// ---------------- device scratch ----------------
__device__ __half g_qt[(size_t)BB * 1536];  // q-tilde (fp16)
__device__ __half g_c [(size_t)BB * 1536];  // context (fp16)
__device__ __half g_ao[(size_t)BB * 384];   // attn out pre-fc (fp16)
__device__ float  g_pre[(size_t)BB * 384];  // fc+bias+residual (fp32, pre-LN)
__device__ __half g_Mqk[1536 * 256];        // fused Wq*Wk matrix [j][k] (fp16)

// ---------------- prep ----------------
__global__ void __launch_bounds__(256) k_prepm(const float* __restrict__ Wq,
                                               const float* __restrict__ Wk) {
    __shared__ float wk[8 * 96];
    const int tid = threadIdx.x;
    const int j0 = blockIdx.x * 8;
    const int h = j0 / 384;
    const int jj0 = j0 - h * 384;

    for (int i = tid; i < 768; i += 256) {
        int jo = i / 96, d = i - jo * 96;
        wk[jo * 96 + d] = Wk[(size_t)(h * 96 + d) * 384 + jj0 + jo];
    }
    __syncthreads();

    const int k = tid;
    const int keff = (k < 128) ? k : k + 128;
    float acc[8] = {};
    for (int d = 0; d < 96; ++d) {
        float wq = __ldg(&Wq[(size_t)(h * 96 + d) * 384 + keff]);
        #pragma unroll
        for (int jo = 0; jo < 8; ++jo)
            acc[jo] = fmaf(wq, wk[jo * 96 + d], acc[jo]);
    }
    #pragma unroll
    for (int jo = 0; jo < 8; ++jo)
        g_Mqk[(size_t)(j0 + jo) * 256 + k] = __float2half_rn(acc[jo]);
}

// ---------- fp16 mma m16n8k16 ----------
__device__ __forceinline__ void mma16(float* c, unsigned a0, unsigned a1, unsigned a2,
                                      unsigned a3, unsigned b0, unsigned b1) {
    asm volatile(
        "mma.sync.aligned.m16n8k16.row.col.f32.f16.f16.f32 "
        "{%0,%1,%2,%3}, {%4,%5,%6,%7}, {%8,%9}, {%0,%1,%2,%3};"
        : "+f"(c[0]), "+f"(c[1]), "+f"(c[2]), "+f"(c[3])
        : "r"(a0), "r"(a1), "r"(a2), "r"(a3), "r"(b0), "r"(b1));
}

template<int NT>
__device__ __forceinline__ void mma16_warp2(float* acc, const __half* sa, const __half* sbt,
                                            int lane) {
    const int grp = lane >> 2, tig = lane & 3;
    #pragma unroll
    for (int ks = 0; ks < 2; ++ks) {
        const __half* ap0 = sa + grp * 40 + ks * 16 + tig * 2;
        const __half* ap1 = ap0 + 16 * 40;
        unsigned a00 = *(const unsigned*)ap0;
        unsigned a01 = *(const unsigned*)(ap0 + 320);
        unsigned a02 = *(const unsigned*)(ap0 + 8);
        unsigned a03 = *(const unsigned*)(ap0 + 328);
        unsigned a10 = *(const unsigned*)ap1;
        unsigned a11 = *(const unsigned*)(ap1 + 320);
        unsigned a12 = *(const unsigned*)(ap1 + 8);
        unsigned a13 = *(const unsigned*)(ap1 + 328);
        #pragma unroll
        for (int nt = 0; nt < NT; ++nt) {
            const __half* bp = sbt + (nt * 8 + grp) * 40 + ks * 16 + tig * 2;
            unsigned b0 = *(const unsigned*)bp;
            unsigned b1 = *(const unsigned*)(bp + 8);
            mma16(acc + nt * 4, a00, a01, a02, a03, b0, b1);
            mma16(acc + (NT + nt) * 4, a10, a11, a12, a13, b0, b1);
        }
    }
}

template<int NT>
__device__ __forceinline__ void mma16_warp(float* acc, const __half* sa, const __half* sbt,
                                           int lane) {
    const int grp = lane >> 2, tig = lane & 3;
    #pragma unroll
    for (int ks = 0; ks < 2; ++ks) {
        const __half* ap0 = sa + grp * 40 + ks * 16 + tig * 2;
        unsigned a00 = *(const unsigned*)ap0;
        unsigned a01 = *(const unsigned*)(ap0 + 320);
        unsigned a02 = *(const unsigned*)(ap0 + 8);
        unsigned a03 = *(const unsigned*)(ap0 + 328);
        #pragma unroll
        for (int nt = 0; nt < NT; ++nt) {
            const __half* bp = sbt + (nt * 8 + grp) * 40 + ks * 16 + tig * 2;
            unsigned b0 = *(const unsigned*)bp;
            unsigned b1 = *(const unsigned*)(bp + 8);
            mma16(acc + nt * 4, a00, a01, a02, a03, b0, b1);
        }
    }
}

// global loaders (registers) + buffered stagers
#define LOADB(W, COLB, KS, KT)                                                \
    _Pragma("unroll")                                                         \
    for (int jj = 0; jj < 3; ++jj) {                                          \
        int qidx = tid + 256 * jj, col = qidx >> 3, q = qidx & 7;             \
        breg[jj] = *(const float4*)&(W)[(size_t)((COLB) + col) * (KS) + (KT) + q * 4]; \
    }
#define STSB2(DST)                                                            \
    _Pragma("unroll")                                                         \
    for (int jj = 0; jj < 3; ++jj) {                                          \
        int qidx = tid + 256 * jj, col = qidx >> 3, q = qidx & 7;             \
        float4 v = breg[jj];                                                  \
        *(__half2*)&(DST)[col * 40 + q * 4]     = __floats2half2_rn(v.x, v.y); \
        *(__half2*)&(DST)[col * 40 + q * 4 + 2] = __floats2half2_rn(v.z, v.w); \
    }
#define LOADA_H(SRC, RSTRIDE, ROWB, KT)                                       \
    _Pragma("unroll")                                                         \
    for (int j = 0; j < 8; ++j)                                               \
        aregu[j] = *(const unsigned*)&(SRC)[(size_t)((ROWB) + rowb + 16 * j) * (RSTRIDE) + (KT) + 2 * kp];
#define STSA_H2(DST)                                                          \
    _Pragma("unroll")                                                         \
    for (int j = 0; j < 8; ++j)                                               \
        *(unsigned*)&(DST)[(rowb + 16 * j) * 40 + 2 * kp] = aregu[j];

// ---------------- k_qt: g_qt[B x 1536] = A_eff[B x 256] @ M_qk^T (double-buffered) ----------------
__global__ void __launch_bounds__(256, 2) k_qt(const float* __restrict__ src,
                                               const float* __restrict__ src_ts,
                                               const float* __restrict__ freq,
                                               const float* __restrict__ phase) {
    __shared__ __align__(16) __half saf[2][128 * 40];
    __shared__ __align__(16) __half sbt[2][96 * 40];
    __shared__ float sts[128];
    const int tid = threadIdx.x, lane = tid & 31, wid = tid >> 5;
    const int bt = blockIdx.x >> 4, cq = blockIdx.x & 15;
    const int b0 = bt * 128, c0 = cq * 96;
    const int kk = tid & 31, row0 = tid >> 5;
    const int rslab = (wid >> 1) * 32, chalf = (wid & 1) * 48;

    if (tid < 128) sts[tid] = src_ts[b0 + tid];
    __syncthreads();

    float areg[16]; uint2 bregu[3];
    #define LOADA_QT(KT) do {                                                 \
        int m = (KT) + kk;                                                    \
        if (m < 128) {                                                        \
            _Pragma("unroll")                                                 \
            for (int j = 0; j < 16; ++j)                                      \
                areg[j] = src[(size_t)(b0 + row0 + 8 * j) * 128 + m];         \
        } else {                                                              \
            float f = freq[m - 128], ph = phase[m - 128];                     \
            _Pragma("unroll")                                                 \
            for (int j = 0; j < 16; ++j)                                      \
                areg[j] = __cosf(sts[row0 + 8 * j] * f + ph);                 \
        } } while (0)
    #define LOADB_QT(KT)                                                      \
        _Pragma("unroll")                                                     \
        for (int jj = 0; jj < 3; ++jj) {                                      \
            int qidx = tid + 256 * jj, col = qidx >> 3, q = qidx & 7;         \
            bregu[jj] = *(const uint2*)&g_Mqk[(size_t)(c0 + col) * 256 + (KT) + q * 4]; \
        }
    #define STSA_QT(DST)                                                      \
        _Pragma("unroll")                                                     \
        for (int j = 0; j < 16; ++j)                                          \
            (DST)[(row0 + 8 * j) * 40 + kk] = __float2half_rn(areg[j]);
    #define STSB_QT(DST)                                                      \
        _Pragma("unroll")                                                     \
        for (int jj = 0; jj < 3; ++jj) {                                      \
            int qidx = tid + 256 * jj, col = qidx >> 3, q = qidx & 7;         \
            *(uint2*)&(DST)[col * 40 + q * 4] = bregu[jj];                    \
        }

    LOADA_QT(0); LOADB_QT(0);
    STSA_QT(saf[0]); STSB_QT(sbt[0]);
    __syncthreads();
    float acc[48] = {};
    for (int t = 0; t < 8; ++t) {
        if (t < 7) { LOADA_QT((t + 1) * 32); LOADB_QT((t + 1) * 32); }
        mma16_warp2<6>(acc, saf[t & 1] + rslab * 40, sbt[t & 1] + chalf * 40, lane);
        if (t < 7) { STSA_QT(saf[(t + 1) & 1]); STSB_QT(sbt[(t + 1) & 1]); }
        __syncthreads();
    }
    const int grp = lane >> 2, tig = lane & 3;
    const int r0 = b0 + rslab + grp;
    #pragma unroll
    for (int nt = 0; nt < 6; ++nt) {
        int j = c0 + chalf + nt * 8 + tig * 2;
        *(__half2*)&g_qt[(size_t)r0 * 1536 + j]        = __floats2half2_rn(acc[nt*4+0], acc[nt*4+1]);
        *(__half2*)&g_qt[(size_t)(r0 + 8) * 1536 + j]  = __floats2half2_rn(acc[nt*4+2], acc[nt*4+3]);
        *(__half2*)&g_qt[(size_t)(r0 + 16) * 1536 + j] = __floats2half2_rn(acc[(6+nt)*4+0], acc[(6+nt)*4+1]);
        *(__half2*)&g_qt[(size_t)(r0 + 24) * 1536 + j] = __floats2half2_rn(acc[(6+nt)*4+2], acc[(6+nt)*4+3]);
    }
    #undef LOADA_QT
    #undef LOADB_QT
    #undef STSA_QT
    #undef STSB_QT
}

// ---------------- attention core: one block per batch, fp16 smem (R13) ----------------
__global__ void __launch_bounds__(256) k_attn(const float* __restrict__ seq,
                                              const float* __restrict__ seq_e,
                                              const float* __restrict__ seq_ts,
                                              const unsigned int* __restrict__ mask,
                                              const float* __restrict__ freq,
                                              const float* __restrict__ phase,
                                              float* __restrict__ attn_out) {
    __shared__ __align__(16) __half kin[NN * 384];
    __shared__ __align__(16) __half qts[1536];
    __shared__ float sc[HH][NN];
    __shared__ float pp[HH][NN];
    const int b = blockIdx.x;
    const int tid = threadIdx.x;
    const int w = tid >> 5, lane = tid & 31;

    const float4* seq4   = (const float4*)seq;
    const float4* seq_e4 = (const float4*)seq_e;
    for (int idx = tid; idx < NN * 32; idx += 256) {
        int n = idx >> 5, q = idx & 31;
        float4 a = seq4  [((size_t)b * NN + n) * 32 + q];
        float4 e = seq_e4[((size_t)b * NN + n) * 32 + q];
        *(__half2*)&kin[n * 384 + q * 4]           = __floats2half2_rn(a.x, a.y);
        *(__half2*)&kin[n * 384 + q * 4 + 2]       = __floats2half2_rn(a.z, a.w);
        *(__half2*)&kin[n * 384 + 128 + q * 4]     = __floats2half2_rn(e.x, e.y);
        *(__half2*)&kin[n * 384 + 128 + q * 4 + 2] = __floats2half2_rn(e.z, e.w);
    }
    for (int idx = tid; idx < NN * 128; idx += 256) {
        int n = idx >> 7, d = idx & 127;
        kin[n * 384 + 256 + d] = __float2half_rn(__cosf(seq_ts[b * NN + n] * freq[d] + phase[d]));
    }
    const uint4* qt4 = (const uint4*)(g_qt + (size_t)b * 1536);
    for (int idx = tid; idx < 192; idx += 256)
        *(uint4*)&qts[idx * 8] = qt4[idx];
    __syncthreads();

    const __half2* kin2 = (const __half2*)kin;
    const __half2* qts2 = (const __half2*)qts;

    for (int p = w; p < HH * NN; p += 8) {
        int h = p / NN, n = p - h * NN;
        float partial = 0.f;
        #pragma unroll
        for (int t = 0; t < 6; ++t) {
            int e = lane + 32 * t;
            float2 qf = __half22float2(qts2[h * 192 + e]);
            float2 kf = __half22float2(kin2[n * 192 + e]);
            partial = fmaf(qf.x, kf.x, partial);
            partial = fmaf(qf.y, kf.y, partial);
        }
        #pragma unroll
        for (int off = 16; off; off >>= 1)
            partial += __shfl_xor_sync(0xffffffffu, partial, off);
        if (lane == 0) {
            float s = partial * SCALE;
            if (mask[b * NN + n] != 0u) s = -1.0e10f;
            sc[h][n] = s;
        }
    }
    __syncthreads();

    if (w < HH) {
        float v = (lane < NN) ? sc[w][lane] : -3.0e38f;
        float mx = v;
        #pragma unroll
        for (int off = 16; off; off >>= 1)
            mx = fmaxf(mx, __shfl_xor_sync(0xffffffffu, mx, off));
        float e = (lane < NN) ? expf(v - mx) : 0.f;
        float s = e;
        #pragma unroll
        for (int off = 16; off; off >>= 1)
            s += __shfl_xor_sync(0xffffffffu, s, off);
        float prob = e / s;
        if (lane < NN) {
            pp[w][lane] = prob;
            attn_out[((size_t)w * BB + b) * NN + lane] = prob;
        }
    }
    __syncthreads();

    __half2* gc2 = (__half2*)(g_c + (size_t)b * 1536);
    for (int idx = tid; idx < 768; idx += 256) {
        int h = idx / 192, e = idx - h * 192;
        float sx = 0.f, sy = 0.f;
        #pragma unroll
        for (int n = 0; n < NN; ++n) {
            float2 kf = __half22float2(kin2[n * 192 + e]);
            float pr = pp[h][n];
            sx = fmaf(pr, kf.x, sx);
            sy = fmaf(pr, kf.y, sy);
        }
        gc2[idx] = __floats2half2_rn(sx, sy);
    }
}

// ---------------- k_vout: g_ao head slab = g_c_h[B x 384] @ Wv_h^T (double-buffered) ----------------
__global__ void __launch_bounds__(256, 2) k_vout(const float* __restrict__ Wv) {
    __shared__ __align__(16) __half saf[2][128 * 40];
    __shared__ __align__(16) __half sbt[2][96 * 40];
    const int tid = threadIdx.x, lane = tid & 31, wid = tid >> 5;
    const int bt = blockIdx.x >> 2, h = blockIdx.x & 3;
    const int b0 = bt * 128;
    const int rowb = tid >> 4, kp = tid & 15;
    const int rslab = (wid >> 1) * 32, chalf = (wid & 1) * 48;

    unsigned aregu[8]; float4 breg[3];
    LOADA_H(g_c, 1536, b0, h * 384 + 0); LOADB(Wv, h * 96, 384, 0);
    STSA_H2(saf[0]); STSB2(sbt[0]);
    __syncthreads();
    float acc[48] = {};
    for (int t = 0; t < 12; ++t) {
        if (t < 11) {
            LOADA_H(g_c, 1536, b0, h * 384 + (t + 1) * 32);
            LOADB(Wv, h * 96, 384, (t + 1) * 32);
        }
        mma16_warp2<6>(acc, saf[t & 1] + rslab * 40, sbt[t & 1] + chalf * 40, lane);
        if (t < 11) { STSA_H2(saf[(t + 1) & 1]); STSB2(sbt[(t + 1) & 1]); }
        __syncthreads();
    }
    const int grp = lane >> 2, tig = lane & 3;
    const int r0 = b0 + rslab + grp;
    #pragma unroll
    for (int nt = 0; nt < 6; ++nt) {
        int col = h * 96 + chalf + nt * 8 + tig * 2;
        *(__half2*)&g_ao[(size_t)r0 * 384 + col]        = __floats2half2_rn(acc[nt*4+0], acc[nt*4+1]);
        *(__half2*)&g_ao[(size_t)(r0 + 8) * 384 + col]  = __floats2half2_rn(acc[nt*4+2], acc[nt*4+3]);
        *(__half2*)&g_ao[(size_t)(r0 + 16) * 384 + col] = __floats2half2_rn(acc[(6+nt)*4+0], acc[(6+nt)*4+1]);
        *(__half2*)&g_ao[(size_t)(r0 + 24) * 384 + col] = __floats2half2_rn(acc[(6+nt)*4+2], acc[(6+nt)*4+3]);
    }
}

// ---------------- k_fc: g_pre = g_ao @ fc_w^T + b + residual (double-buffered) ----------------
__global__ void __launch_bounds__(256, 2) k_fc(const float* __restrict__ src,
                                               const float* __restrict__ src_ts,
                                               const float* __restrict__ freq,
                                               const float* __restrict__ phase,
                                               const float* __restrict__ fc_w,
                                               const float* __restrict__ fc_b) {
    __shared__ __align__(16) __half saf[2][128 * 40];
    __shared__ __align__(16) __half sbt[2][96 * 40];
    const int tid = threadIdx.x, lane = tid & 31, wid = tid >> 5;
    const int bt = blockIdx.x >> 2, cq = blockIdx.x & 3;
    const int b0 = bt * 128, c0 = cq * 96;
    const int rowb = tid >> 4, kp = tid & 15;
    const int rslab = (wid >> 1) * 32, chalf = (wid & 1) * 48;

    unsigned aregu[8]; float4 breg[3];
    LOADA_H(g_ao, 384, b0, 0); LOADB(fc_w, c0, 384, 0);
    STSA_H2(saf[0]); STSB2(sbt[0]);
    __syncthreads();
    float acc[48] = {};
    for (int t = 0; t < 12; ++t) {
        if (t < 11) {
            LOADA_H(g_ao, 384, b0, (t + 1) * 32);
            LOADB(fc_w, c0, 384, (t + 1) * 32);
        }
        mma16_warp2<6>(acc, saf[t & 1] + rslab * 40, sbt[t & 1] + chalf * 40, lane);
        if (t < 11) { STSA_H2(saf[(t + 1) & 1]); STSB2(sbt[(t + 1) & 1]); }
        __syncthreads();
    }
    const int grp = lane >> 2, tig = lane & 3;
    const int r0 = b0 + rslab + grp;
    float tsv[4];
    #pragma unroll
    for (int s = 0; s < 4; ++s) tsv[s] = src_ts[r0 + 8 * s];
    #pragma unroll
    for (int s = 0; s < 4; ++s) {
        const int rr = r0 + 8 * s;
        const int ab = (s >> 1) * 24 + (s & 1) * 2;
        #pragma unroll
        for (int nt = 0; nt < 6; ++nt) {
            #pragma unroll
            for (int cc = 0; cc < 2; ++cc) {
                int col = c0 + chalf + nt * 8 + tig * 2 + cc;
                float v = acc[ab + nt * 4 + cc] + fc_b[col];
                if (col < 128) {
                    v += src[(size_t)rr * 128 + col];
                } else if (col >= 256) {
                    int d = col - 256;
                    v += __cosf(tsv[s] * freq[d] + phase[d]);
                }
                g_pre[(size_t)rr * 384 + col] = v;
            }
        }
    }
}

// ---------------- k_mlp: two-pass LN + fp16 tensor-core MLP, 64 rows/block (R13) ----------------
__global__ void __launch_bounds__(256) k_mlp(const float* __restrict__ src,
                                             const float* __restrict__ ln_g,
                                             const float* __restrict__ ln_b,
                                             const float* __restrict__ m1_w,
                                             const float* __restrict__ m1_b,
                                             const float* __restrict__ m2_w,
                                             const float* __restrict__ m2_b,
                                             float* __restrict__ y) {
    __shared__ __align__(16) __half saf[64 * 40];
    __shared__ __align__(16) __half sbtm[128 * 40];
    __shared__ __align__(16) __half hst[4 * 64 * 40];
    __shared__ float smu[64], sinv[64];
    const int tid = threadIdx.x, lane = tid & 31, wid = tid >> 5;
    const int b0 = blockIdx.x * 64;
    const int kk = tid & 31, row0 = tid >> 5;

    for (int rr = 0; rr < 8; ++rr) {
        int row = wid * 8 + rr;
        const float* pr = g_pre + (size_t)(b0 + row) * 384;
        float s1 = 0.f, s2 = 0.f;
        #pragma unroll
        for (int t = 0; t < 12; ++t) {
            float v = pr[lane + 32 * t];
            s1 += v; s2 = fmaf(v, v, s2);
        }
        #pragma unroll
        for (int off = 16; off; off >>= 1) {
            s1 += __shfl_xor_sync(0xffffffffu, s1, off);
            s2 += __shfl_xor_sync(0xffffffffu, s2, off);
        }
        if (lane == 0) {
            float mu = s1 * (1.f / 384.f);
            float var = s2 * (1.f / 384.f) - mu * mu;
            smu[row] = mu;
            sinv[row] = rsqrtf(var + 1e-5f);
        }
    }
    __syncthreads();

    float areg[8]; float4 breg4[4];
    #define LOADB4(W, KS, KT)                                                  \
        _Pragma("unroll")                                                      \
        for (int jj = 0; jj < 4; ++jj) {                                       \
            int qidx = tid + 256 * jj, col = qidx >> 3, q = qidx & 7;          \
            breg4[jj] = *(const float4*)&(W)[(size_t)col * (KS) + (KT) + q * 4]; \
        }
    #define STSB4()                                                            \
        _Pragma("unroll")                                                      \
        for (int jj = 0; jj < 4; ++jj) {                                       \
            int qidx = tid + 256 * jj, col = qidx >> 3, q = qidx & 7;          \
            float4 v = breg4[jj];                                              \
            *(__half2*)&sbtm[col * 40 + q * 4]     = __floats2half2_rn(v.x, v.y); \
            *(__half2*)&sbtm[col * 40 + q * 4 + 2] = __floats2half2_rn(v.z, v.w); \
        }
    #define LOADA_X(KT) do {                                                   \
        int k_ = (KT) + kk;                                                    \
        if (k_ < 384) {                                                        \
            _Pragma("unroll")                                                  \
            for (int j = 0; j < 8; ++j)                                        \
                areg[j] = g_pre[(size_t)(b0 + row0 + 8 * j) * 384 + k_];       \
        } else {                                                               \
            int d_ = k_ - 384;                                                 \
            _Pragma("unroll")                                                  \
            for (int j = 0; j < 8; ++j)                                        \
                areg[j] = src[(size_t)(b0 + row0 + 8 * j) * 128 + d_];         \
        } } while (0)
    #define STSA_X(KT) do {                                                    \
        int k_ = (KT) + kk;                                                    \
        if (k_ < 384) {                                                        \
            float lng = ln_g[k_], lnb = ln_b[k_];                              \
            _Pragma("unroll")                                                  \
            for (int j = 0; j < 8; ++j) {                                      \
                int row = row0 + 8 * j;                                        \
                float v = (areg[j] - smu[row]) * sinv[row] * lng + lnb;        \
                saf[row * 40 + kk] = __float2half_rn(v);                       \
            }                                                                  \
        } else {                                                               \
            _Pragma("unroll")                                                  \
            for (int j = 0; j < 8; ++j)                                        \
                saf[(row0 + 8 * j) * 40 + kk] = __float2half_rn(areg[j]);      \
        } } while (0)

    const int grp = lane >> 2, tig = lane & 3;
    const int rslab = (wid >> 1) * 16, chalf = (wid & 1) * 64;
    const int r0 = rslab + grp;

    LOADA_X(0); LOADB4(m1_w, 512, 0);
    float acc[32] = {};
    for (int t = 0; t < 16; ++t) {
        __syncthreads();
        STSA_X(t * 32); STSB4();
        __syncthreads();
        if (t < 15) { LOADA_X((t + 1) * 32); LOADB4(m1_w, 512, (t + 1) * 32); }
        mma16_warp<8>(acc, saf + rslab * 40, sbtm + chalf * 40, lane);
    }
    #pragma unroll
    for (int nt = 0; nt < 8; ++nt) {
        int col = chalf + nt * 8 + tig * 2;
        float b1a = m1_b[col], b1b = m1_b[col + 1];
        __half* hb = hst + (col >> 5) * 2560 + (col & 31);
        *(__half2*)&hb[r0 * 40] =
            __floats2half2_rn(fmaxf(acc[nt*4+0] + b1a, 0.f), fmaxf(acc[nt*4+1] + b1b, 0.f));
        *(__half2*)&hb[(r0 + 8) * 40] =
            __floats2half2_rn(fmaxf(acc[nt*4+2] + b1a, 0.f), fmaxf(acc[nt*4+3] + b1b, 0.f));
    }
    #pragma unroll
    for (int i = 0; i < 32; ++i) acc[i] = 0.f;

    for (int t = 0; t < 4; ++t) {
        LOADB4(m2_w, 128, t * 32);
        __syncthreads();
        STSB4();
        __syncthreads();
        mma16_warp<8>(acc, hst + t * 2560 + rslab * 40, sbtm + chalf * 40, lane);
    }
    #pragma unroll
    for (int nt = 0; nt < 8; ++nt) {
        int col = chalf + nt * 8 + tig * 2;
        float b2a = m2_b[col], b2b = m2_b[col + 1];
        *(float2*)&y[(size_t)(b0 + r0) * 128 + col] =
            make_float2(acc[nt*4+0] + b2a, acc[nt*4+1] + b2b);
        *(float2*)&y[(size_t)(b0 + r0 + 8) * 128 + col] =
            make_float2(acc[nt*4+2] + b2a, acc[nt*4+3] + b2b);
    }
    #undef LOADB4
    #undef STSB4
    #undef LOADA_X
    #undef STSA_X
}

// ---------------- launch ----------------
extern "C" void kernel_launch(void* const* d_in, const int* in_sizes, int n_in,
                              void* d_out, int out_size) {
    const float* src    = (const float*)d_in[0];
    const float* seq    = (const float*)d_in[1];
    const float* seq_e  = (const float*)d_in[2];
    const float* src_ts = (const float*)d_in[3];
    const float* seq_ts = (const float*)d_in[4];
    const unsigned int* mask = (const unsigned int*)d_in[5];
    const float* freq   = (const float*)d_in[6];
    const float* phase  = (const float*)d_in[7];
    const float* Wq     = (const float*)d_in[8];
    const float* Wk     = (const float*)d_in[9];
    const float* Wv     = (const float*)d_in[10];
    const float* fc_w   = (const float*)d_in[11];
    const float* fc_b   = (const float*)d_in[12];
    const float* ln_g   = (const float*)d_in[13];
    const float* ln_b   = (const float*)d_in[14];
    const float* m1_w   = (const float*)d_in[15];
    const float* m1_b   = (const float*)d_in[16];
    const float* m2_w   = (const float*)d_in[17];
    const float* m2_b   = (const float*)d_in[18];

    float* y_out = (float*)d_out;
    float* attn_out = y_out + (size_t)BB * DD;

    k_prepm <<<192, 256>>>(Wq, Wk);
    k_qt    <<<2048, 256>>>(src, src_ts, freq, phase);
    k_attn  <<<BB, 256>>>(seq, seq_e, seq_ts, mask, freq, phase, attn_out);
    k_vout  <<<512, 256>>>(Wv);
    k_fc    <<<512, 256>>>(src, src_ts, freq, phase, fc_w, fc_b);
    k_mlp   <<<256, 256>>>(src, ln_g, ln_b, m1_w, m1_b, m2_w, m2_b, y_out);
}

// round 16
// speedup vs baseline: 1.0922x; 1.0768x over previous
#include <cuda_runtime.h>
#include <cuda_fp16.h>
#include <math.h>

#define BB 16384
#define NN 20
#define DD 128
#define HH 4
#define SCALE 0.1020620726159658f /* 1/sqrt(96) */

// ---------------- device scratch ----------------
__device__ __half g_qt[(size_t)BB * 1536];  // q-tilde (fp16)
__device__ __half g_c [(size_t)BB * 1536];  // context (fp16)
__device__ __half g_ao[(size_t)BB * 384];   // attn out pre-fc (fp16)
__device__ float  g_pre[(size_t)BB * 384];  // fc+bias+residual (fp32, pre-LN)
__device__ __half g_Mqk[1536 * 256];        // fused Wq*Wk matrix [j][k] (fp16)
__device__ __half g_te[(size_t)BB * 128];   // src time-encoding (fp16)

// ---------------- prep ----------------
__global__ void __launch_bounds__(256) k_prepm(const float* __restrict__ Wq,
                                               const float* __restrict__ Wk) {
    __shared__ float wk[8 * 96];
    const int tid = threadIdx.x;
    const int j0 = blockIdx.x * 8;
    const int h = j0 / 384;
    const int jj0 = j0 - h * 384;

    for (int i = tid; i < 768; i += 256) {
        int jo = i / 96, d = i - jo * 96;
        wk[jo * 96 + d] = Wk[(size_t)(h * 96 + d) * 384 + jj0 + jo];
    }
    __syncthreads();

    const int k = tid;
    const int keff = (k < 128) ? k : k + 128;
    float acc[8] = {};
    for (int d = 0; d < 96; ++d) {
        float wq = __ldg(&Wq[(size_t)(h * 96 + d) * 384 + keff]);
        #pragma unroll
        for (int jo = 0; jo < 8; ++jo)
            acc[jo] = fmaf(wq, wk[jo * 96 + d], acc[jo]);
    }
    #pragma unroll
    for (int jo = 0; jo < 8; ++jo)
        g_Mqk[(size_t)(j0 + jo) * 256 + k] = __float2half_rn(acc[jo]);
}

// ---------------- k_te: src time-encoding, computed once ----------------
__global__ void __launch_bounds__(256) k_te(const float* __restrict__ src_ts,
                                            const float* __restrict__ freq,
                                            const float* __restrict__ phase) {
    int i = blockIdx.x * 256 + threadIdx.x;
    int b = i >> 7, d = i & 127;
    g_te[i] = __float2half_rn(__cosf(src_ts[b] * freq[d] + phase[d]));
}

// ---------- fp16 mma m16n8k16 ----------
__device__ __forceinline__ void mma16(float* c, unsigned a0, unsigned a1, unsigned a2,
                                      unsigned a3, unsigned b0, unsigned b1) {
    asm volatile(
        "mma.sync.aligned.m16n8k16.row.col.f32.f16.f16.f32 "
        "{%0,%1,%2,%3}, {%4,%5,%6,%7}, {%8,%9}, {%0,%1,%2,%3};"
        : "+f"(c[0]), "+f"(c[1]), "+f"(c[2]), "+f"(c[3])
        : "r"(a0), "r"(a1), "r"(a2), "r"(a3), "r"(b0), "r"(b1));
}

template<int NT>
__device__ __forceinline__ void mma16_warp2(float* acc, const __half* sa, const __half* sbt,
                                            int lane) {
    const int grp = lane >> 2, tig = lane & 3;
    #pragma unroll
    for (int ks = 0; ks < 2; ++ks) {
        const __half* ap0 = sa + grp * 40 + ks * 16 + tig * 2;
        const __half* ap1 = ap0 + 16 * 40;
        unsigned a00 = *(const unsigned*)ap0;
        unsigned a01 = *(const unsigned*)(ap0 + 320);
        unsigned a02 = *(const unsigned*)(ap0 + 8);
        unsigned a03 = *(const unsigned*)(ap0 + 328);
        unsigned a10 = *(const unsigned*)ap1;
        unsigned a11 = *(const unsigned*)(ap1 + 320);
        unsigned a12 = *(const unsigned*)(ap1 + 8);
        unsigned a13 = *(const unsigned*)(ap1 + 328);
        #pragma unroll
        for (int nt = 0; nt < NT; ++nt) {
            const __half* bp = sbt + (nt * 8 + grp) * 40 + ks * 16 + tig * 2;
            unsigned b0 = *(const unsigned*)bp;
            unsigned b1 = *(const unsigned*)(bp + 8);
            mma16(acc + nt * 4, a00, a01, a02, a03, b0, b1);
            mma16(acc + (NT + nt) * 4, a10, a11, a12, a13, b0, b1);
        }
    }
}

template<int NT>
__device__ __forceinline__ void mma16_warp(float* acc, const __half* sa, const __half* sbt,
                                           int lane) {
    const int grp = lane >> 2, tig = lane & 3;
    #pragma unroll
    for (int ks = 0; ks < 2; ++ks) {
        const __half* ap0 = sa + grp * 40 + ks * 16 + tig * 2;
        unsigned a00 = *(const unsigned*)ap0;
        unsigned a01 = *(const unsigned*)(ap0 + 320);
        unsigned a02 = *(const unsigned*)(ap0 + 8);
        unsigned a03 = *(const unsigned*)(ap0 + 328);
        #pragma unroll
        for (int nt = 0; nt < NT; ++nt) {
            const __half* bp = sbt + (nt * 8 + grp) * 40 + ks * 16 + tig * 2;
            unsigned b0 = *(const unsigned*)bp;
            unsigned b1 = *(const unsigned*)(bp + 8);
            mma16(acc + nt * 4, a00, a01, a02, a03, b0, b1);
        }
    }
}

// global loaders (registers) + buffered stagers
#define LOADB(W, COLB, KS, KT)                                                \
    _Pragma("unroll")                                                         \
    for (int jj = 0; jj < 3; ++jj) {                                          \
        int qidx = tid + 256 * jj, col = qidx >> 3, q = qidx & 7;             \
        breg[jj] = *(const float4*)&(W)[(size_t)((COLB) + col) * (KS) + (KT) + q * 4]; \
    }
#define STSB2(DST)                                                            \
    _Pragma("unroll")                                                         \
    for (int jj = 0; jj < 3; ++jj) {                                          \
        int qidx = tid + 256 * jj, col = qidx >> 3, q = qidx & 7;             \
        float4 v = breg[jj];                                                  \
        *(__half2*)&(DST)[col * 40 + q * 4]     = __floats2half2_rn(v.x, v.y); \
        *(__half2*)&(DST)[col * 40 + q * 4 + 2] = __floats2half2_rn(v.z, v.w); \
    }
#define LOADA_H(SRC, RSTRIDE, ROWB, KT)                                       \
    _Pragma("unroll")                                                         \
    for (int j = 0; j < 8; ++j)                                               \
        aregu[j] = *(const unsigned*)&(SRC)[(size_t)((ROWB) + rowb + 16 * j) * (RSTRIDE) + (KT) + 2 * kp];
#define STSA_H2(DST)                                                          \
    _Pragma("unroll")                                                         \
    for (int j = 0; j < 8; ++j)                                               \
        *(unsigned*)&(DST)[(rowb + 16 * j) * 40 + 2 * kp] = aregu[j];

// ---------------- k_qt: g_qt[B x 1536] = A_eff[B x 256] @ M_qk^T (double-buffered) ----------------
__global__ void __launch_bounds__(256, 2) k_qt(const float* __restrict__ src) {
    __shared__ __align__(16) __half saf[2][128 * 40];
    __shared__ __align__(16) __half sbt[2][96 * 40];
    const int tid = threadIdx.x, lane = tid & 31, wid = tid >> 5;
    const int bt = blockIdx.x >> 4, cq = blockIdx.x & 15;
    const int b0 = bt * 128, c0 = cq * 96;
    const int kk = tid & 31, row0 = tid >> 5;
    const int rslab = (wid >> 1) * 32, chalf = (wid & 1) * 48;

    float areg[16]; uint2 bregu[3];
    #define LOADA_QT(KT) do {                                                 \
        int m = (KT) + kk;                                                    \
        if (m < 128) {                                                        \
            _Pragma("unroll")                                                 \
            for (int j = 0; j < 16; ++j)                                      \
                areg[j] = src[(size_t)(b0 + row0 + 8 * j) * 128 + m];         \
        } else {                                                              \
            int d_ = m - 128;                                                 \
            _Pragma("unroll")                                                 \
            for (int j = 0; j < 16; ++j)                                      \
                areg[j] = __half2float(g_te[(size_t)(b0 + row0 + 8 * j) * 128 + d_]); \
        } } while (0)
    #define LOADB_QT(KT)                                                      \
        _Pragma("unroll")                                                     \
        for (int jj = 0; jj < 3; ++jj) {                                      \
            int qidx = tid + 256 * jj, col = qidx >> 3, q = qidx & 7;         \
            bregu[jj] = *(const uint2*)&g_Mqk[(size_t)(c0 + col) * 256 + (KT) + q * 4]; \
        }
    #define STSA_QT(DST)                                                      \
        _Pragma("unroll")                                                     \
        for (int j = 0; j < 16; ++j)                                          \
            (DST)[(row0 + 8 * j) * 40 + kk] = __float2half_rn(areg[j]);
    #define STSB_QT(DST)                                                      \
        _Pragma("unroll")                                                     \
        for (int jj = 0; jj < 3; ++jj) {                                      \
            int qidx = tid + 256 * jj, col = qidx >> 3, q = qidx & 7;         \
            *(uint2*)&(DST)[col * 40 + q * 4] = bregu[jj];                    \
        }

    LOADA_QT(0); LOADB_QT(0);
    STSA_QT(saf[0]); STSB_QT(sbt[0]);
    __syncthreads();
    float acc[48] = {};
    for (int t = 0; t < 8; ++t) {
        if (t < 7) { LOADA_QT((t + 1) * 32); LOADB_QT((t + 1) * 32); }
        mma16_warp2<6>(acc, saf[t & 1] + rslab * 40, sbt[t & 1] + chalf * 40, lane);
        if (t < 7) { STSA_QT(saf[(t + 1) & 1]); STSB_QT(sbt[(t + 1) & 1]); }
        __syncthreads();
    }
    const int grp = lane >> 2, tig = lane & 3;
    const int r0 = b0 + rslab + grp;
    #pragma unroll
    for (int nt = 0; nt < 6; ++nt) {
        int j = c0 + chalf + nt * 8 + tig * 2;
        *(__half2*)&g_qt[(size_t)r0 * 1536 + j]        = __floats2half2_rn(acc[nt*4+0], acc[nt*4+1]);
        *(__half2*)&g_qt[(size_t)(r0 + 8) * 1536 + j]  = __floats2half2_rn(acc[nt*4+2], acc[nt*4+3]);
        *(__half2*)&g_qt[(size_t)(r0 + 16) * 1536 + j] = __floats2half2_rn(acc[(6+nt)*4+0], acc[(6+nt)*4+1]);
        *(__half2*)&g_qt[(size_t)(r0 + 24) * 1536 + j] = __floats2half2_rn(acc[(6+nt)*4+2], acc[(6+nt)*4+3]);
    }
    #undef LOADA_QT
    #undef LOADB_QT
    #undef STSA_QT
    #undef STSB_QT
}

// ---------------- attention core: one block per batch, fp16 smem, reduced LDS ----------------
__global__ void __launch_bounds__(256) k_attn(const float* __restrict__ seq,
                                              const float* __restrict__ seq_e,
                                              const float* __restrict__ seq_ts,
                                              const unsigned int* __restrict__ mask,
                                              const float* __restrict__ freq,
                                              const float* __restrict__ phase,
                                              float* __restrict__ attn_out) {
    __shared__ __align__(16) __half kin[NN * 384];
    __shared__ __align__(16) __half qts[1536];
    __shared__ float sc[HH][NN];
    __shared__ float pp[HH][NN];
    const int b = blockIdx.x;
    const int tid = threadIdx.x;
    const int w = tid >> 5, lane = tid & 31;

    const float4* seq4   = (const float4*)seq;
    const float4* seq_e4 = (const float4*)seq_e;
    for (int idx = tid; idx < NN * 32; idx += 256) {
        int n = idx >> 5, q = idx & 31;
        float4 a = seq4  [((size_t)b * NN + n) * 32 + q];
        float4 e = seq_e4[((size_t)b * NN + n) * 32 + q];
        *(__half2*)&kin[n * 384 + q * 4]           = __floats2half2_rn(a.x, a.y);
        *(__half2*)&kin[n * 384 + q * 4 + 2]       = __floats2half2_rn(a.z, a.w);
        *(__half2*)&kin[n * 384 + 128 + q * 4]     = __floats2half2_rn(e.x, e.y);
        *(__half2*)&kin[n * 384 + 128 + q * 4 + 2] = __floats2half2_rn(e.z, e.w);
    }
    for (int idx = tid; idx < NN * 128; idx += 256) {
        int n = idx >> 7, d = idx & 127;
        kin[n * 384 + 256 + d] = __float2half_rn(__cosf(seq_ts[b * NN + n] * freq[d] + phase[d]));
    }
    const uint4* qt4 = (const uint4*)(g_qt + (size_t)b * 1536);
    for (int idx = tid; idx < 192; idx += 256)
        *(uint4*)&qts[idx * 8] = qt4[idx];
    __syncthreads();

    const __half2* kin2 = (const __half2*)kin;
    const __half2* qts2 = (const __half2*)qts;

    // scores: warp w -> head w>>1, n in [(w&1)*10, +10). q fragment hoisted.
    {
        const int h = w >> 1;
        const int nb = (w & 1) * 10;
        float2 qf[6];
        #pragma unroll
        for (int t = 0; t < 6; ++t)
            qf[t] = __half22float2(qts2[h * 192 + lane + 32 * t]);
        #pragma unroll
        for (int nn = 0; nn < 10; ++nn) {
            const int n = nb + nn;
            float partial = 0.f;
            #pragma unroll
            for (int t = 0; t < 6; ++t) {
                float2 kf = __half22float2(kin2[n * 192 + lane + 32 * t]);
                partial = fmaf(qf[t].x, kf.x, partial);
                partial = fmaf(qf[t].y, kf.y, partial);
            }
            #pragma unroll
            for (int off = 16; off; off >>= 1)
                partial += __shfl_xor_sync(0xffffffffu, partial, off);
            if (lane == 0) {
                float s = partial * SCALE;
                if (mask[b * NN + n] != 0u) s = -1.0e10f;
                sc[h][n] = s;
            }
        }
    }
    __syncthreads();

    if (w < HH) {
        float v = (lane < NN) ? sc[w][lane] : -3.0e38f;
        float mx = v;
        #pragma unroll
        for (int off = 16; off; off >>= 1)
            mx = fmaxf(mx, __shfl_xor_sync(0xffffffffu, mx, off));
        float e = (lane < NN) ? expf(v - mx) : 0.f;
        float s = e;
        #pragma unroll
        for (int off = 16; off; off >>= 1)
            s += __shfl_xor_sync(0xffffffffu, s, off);
        float prob = e / s;
        if (lane < NN) {
            pp[w][lane] = prob;
            attn_out[((size_t)w * BB + b) * NN + lane] = prob;
        }
    }
    __syncthreads();

    // context: thread handles head tid>>6, e = (tid&63) + 64j; probs hoisted to regs
    {
        const int h = tid >> 6, e0 = tid & 63;
        float pr[NN];
        #pragma unroll
        for (int n = 0; n < NN; ++n) pr[n] = pp[h][n];
        __half2* gc2 = (__half2*)(g_c + (size_t)b * 1536);
        #pragma unroll
        for (int j = 0; j < 3; ++j) {
            const int e = e0 + 64 * j;
            float sx = 0.f, sy = 0.f;
            #pragma unroll
            for (int n = 0; n < NN; ++n) {
                float2 kf = __half22float2(kin2[n * 192 + e]);
                sx = fmaf(pr[n], kf.x, sx);
                sy = fmaf(pr[n], kf.y, sy);
            }
            gc2[h * 192 + e] = __floats2half2_rn(sx, sy);
        }
    }
}

// ---------------- k_vout: g_ao head slab = g_c_h[B x 384] @ Wv_h^T (double-buffered) ----------------
__global__ void __launch_bounds__(256, 2) k_vout(const float* __restrict__ Wv) {
    __shared__ __align__(16) __half saf[2][128 * 40];
    __shared__ __align__(16) __half sbt[2][96 * 40];
    const int tid = threadIdx.x, lane = tid & 31, wid = tid >> 5;
    const int bt = blockIdx.x >> 2, h = blockIdx.x & 3;
    const int b0 = bt * 128;
    const int rowb = tid >> 4, kp = tid & 15;
    const int rslab = (wid >> 1) * 32, chalf = (wid & 1) * 48;

    unsigned aregu[8]; float4 breg[3];
    LOADA_H(g_c, 1536, b0, h * 384 + 0); LOADB(Wv, h * 96, 384, 0);
    STSA_H2(saf[0]); STSB2(sbt[0]);
    __syncthreads();
    float acc[48] = {};
    for (int t = 0; t < 12; ++t) {
        if (t < 11) {
            LOADA_H(g_c, 1536, b0, h * 384 + (t + 1) * 32);
            LOADB(Wv, h * 96, 384, (t + 1) * 32);
        }
        mma16_warp2<6>(acc, saf[t & 1] + rslab * 40, sbt[t & 1] + chalf * 40, lane);
        if (t < 11) { STSA_H2(saf[(t + 1) & 1]); STSB2(sbt[(t + 1) & 1]); }
        __syncthreads();
    }
    const int grp = lane >> 2, tig = lane & 3;
    const int r0 = b0 + rslab + grp;
    #pragma unroll
    for (int nt = 0; nt < 6; ++nt) {
        int col = h * 96 + chalf + nt * 8 + tig * 2;
        *(__half2*)&g_ao[(size_t)r0 * 384 + col]        = __floats2half2_rn(acc[nt*4+0], acc[nt*4+1]);
        *(__half2*)&g_ao[(size_t)(r0 + 8) * 384 + col]  = __floats2half2_rn(acc[nt*4+2], acc[nt*4+3]);
        *(__half2*)&g_ao[(size_t)(r0 + 16) * 384 + col] = __floats2half2_rn(acc[(6+nt)*4+0], acc[(6+nt)*4+1]);
        *(__half2*)&g_ao[(size_t)(r0 + 24) * 384 + col] = __floats2half2_rn(acc[(6+nt)*4+2], acc[(6+nt)*4+3]);
    }
}

// ---------------- k_fc: g_pre = g_ao @ fc_w^T + b + residual (double-buffered) ----------------
__global__ void __launch_bounds__(256, 2) k_fc(const float* __restrict__ src,
                                               const float* __restrict__ src_ts,
                                               const float* __restrict__ freq,
                                               const float* __restrict__ phase,
                                               const float* __restrict__ fc_w,
                                               const float* __restrict__ fc_b) {
    __shared__ __align__(16) __half saf[2][128 * 40];
    __shared__ __align__(16) __half sbt[2][96 * 40];
    const int tid = threadIdx.x, lane = tid & 31, wid = tid >> 5;
    const int bt = blockIdx.x >> 2, cq = blockIdx.x & 3;
    const int b0 = bt * 128, c0 = cq * 96;
    const int rowb = tid >> 4, kp = tid & 15;
    const int rslab = (wid >> 1) * 32, chalf = (wid & 1) * 48;

    unsigned aregu[8]; float4 breg[3];
    LOADA_H(g_ao, 384, b0, 0); LOADB(fc_w, c0, 384, 0);
    STSA_H2(saf[0]); STSB2(sbt[0]);
    __syncthreads();
    float acc[48] = {};
    for (int t = 0; t < 12; ++t) {
        if (t < 11) {
            LOADA_H(g_ao, 384, b0, (t + 1) * 32);
            LOADB(fc_w, c0, 384, (t + 1) * 32);
        }
        mma16_warp2<6>(acc, saf[t & 1] + rslab * 40, sbt[t & 1] + chalf * 40, lane);
        if (t < 11) { STSA_H2(saf[(t + 1) & 1]); STSB2(sbt[(t + 1) & 1]); }
        __syncthreads();
    }
    const int grp = lane >> 2, tig = lane & 3;
    const int r0 = b0 + rslab + grp;
    float tsv[4];
    #pragma unroll
    for (int s = 0; s < 4; ++s) tsv[s] = src_ts[r0 + 8 * s];
    #pragma unroll
    for (int s = 0; s < 4; ++s) {
        const int rr = r0 + 8 * s;
        const int ab = (s >> 1) * 24 + (s & 1) * 2;
        #pragma unroll
        for (int nt = 0; nt < 6; ++nt) {
            #pragma unroll
            for (int cc = 0; cc < 2; ++cc) {
                int col = c0 + chalf + nt * 8 + tig * 2 + cc;
                float v = acc[ab + nt * 4 + cc] + fc_b[col];
                if (col < 128) {
                    v += src[(size_t)rr * 128 + col];
                } else if (col >= 256) {
                    int d = col - 256;
                    v += __cosf(tsv[s] * freq[d] + phase[d]);
                }
                g_pre[(size_t)rr * 384 + col] = v;
            }
        }
    }
}

// ---------------- k_mlp: two-pass LN + fp16 tensor-core MLP, 64 rows/block ----------------
__global__ void __launch_bounds__(256) k_mlp(const float* __restrict__ src,
                                             const float* __restrict__ ln_g,
                                             const float* __restrict__ ln_b,
                                             const float* __restrict__ m1_w,
                                             const float* __restrict__ m1_b,
                                             const float* __restrict__ m2_w,
                                             const float* __restrict__ m2_b,
                                             float* __restrict__ y) {
    __shared__ __align__(16) __half saf[64 * 40];
    __shared__ __align__(16) __half sbtm[128 * 40];
    __shared__ __align__(16) __half hst[4 * 64 * 40];
    __shared__ float smu[64], sinv[64];
    const int tid = threadIdx.x, lane = tid & 31, wid = tid >> 5;
    const int b0 = blockIdx.x * 64;
    const int kk = tid & 31, row0 = tid >> 5;

    for (int rr = 0; rr < 8; ++rr) {
        int row = wid * 8 + rr;
        const float* pr = g_pre + (size_t)(b0 + row) * 384;
        float s1 = 0.f, s2 = 0.f;
        #pragma unroll
        for (int t = 0; t < 12; ++t) {
            float v = pr[lane + 32 * t];
            s1 += v; s2 = fmaf(v, v, s2);
        }
        #pragma unroll
        for (int off = 16; off; off >>= 1) {
            s1 += __shfl_xor_sync(0xffffffffu, s1, off);
            s2 += __shfl_xor_sync(0xffffffffu, s2, off);
        }
        if (lane == 0) {
            float mu = s1 * (1.f / 384.f);
            float var = s2 * (1.f / 384.f) - mu * mu;
            smu[row] = mu;
            sinv[row] = rsqrtf(var + 1e-5f);
        }
    }
    __syncthreads();

    float areg[8]; float4 breg4[4];
    #define LOADB4(W, KS, KT)                                                  \
        _Pragma("unroll")                                                      \
        for (int jj = 0; jj < 4; ++jj) {                                       \
            int qidx = tid + 256 * jj, col = qidx >> 3, q = qidx & 7;          \
            breg4[jj] = *(const float4*)&(W)[(size_t)col * (KS) + (KT) + q * 4]; \
        }
    #define STSB4()                                                            \
        _Pragma("unroll")                                                      \
        for (int jj = 0; jj < 4; ++jj) {                                       \
            int qidx = tid + 256 * jj, col = qidx >> 3, q = qidx & 7;          \
            float4 v = breg4[jj];                                              \
            *(__half2*)&sbtm[col * 40 + q * 4]     = __floats2half2_rn(v.x, v.y); \
            *(__half2*)&sbtm[col * 40 + q * 4 + 2] = __floats2half2_rn(v.z, v.w); \
        }
    #define LOADA_X(KT) do {                                                   \
        int k_ = (KT) + kk;                                                    \
        if (k_ < 384) {                                                        \
            _Pragma("unroll")                                                  \
            for (int j = 0; j < 8; ++j)                                        \
                areg[j] = g_pre[(size_t)(b0 + row0 + 8 * j) * 384 + k_];       \
        } else {                                                               \
            int d_ = k_ - 384;                                                 \
            _Pragma("unroll")                                                  \
            for (int j = 0; j < 8; ++j)                                        \
                areg[j] = src[(size_t)(b0 + row0 + 8 * j) * 128 + d_];         \
        } } while (0)
    #define STSA_X(KT) do {                                                    \
        int k_ = (KT) + kk;                                                    \
        if (k_ < 384) {                                                        \
            float lng = ln_g[k_], lnb = ln_b[k_];                              \
            _Pragma("unroll")                                                  \
            for (int j = 0; j < 8; ++j) {                                      \
                int row = row0 + 8 * j;                                        \
                float v = (areg[j] - smu[row]) * sinv[row] * lng + lnb;        \
                saf[row * 40 + kk] = __float2half_rn(v);                       \
            }                                                                  \
        } else {                                                               \
            _Pragma("unroll")                                                  \
            for (int j = 0; j < 8; ++j)                                        \
                saf[(row0 + 8 * j) * 40 + kk] = __float2half_rn(areg[j]);      \
        } } while (0)

    const int grp = lane >> 2, tig = lane & 3;
    const int rslab = (wid >> 1) * 16, chalf = (wid & 1) * 64;
    const int r0 = rslab + grp;

    LOADA_X(0); LOADB4(m1_w, 512, 0);
    float acc[32] = {};
    for (int t = 0; t < 16; ++t) {
        __syncthreads();
        STSA_X(t * 32); STSB4();
        __syncthreads();
        if (t < 15) { LOADA_X((t + 1) * 32); LOADB4(m1_w, 512, (t + 1) * 32); }
        mma16_warp<8>(acc, saf + rslab * 40, sbtm + chalf * 40, lane);
    }
    #pragma unroll
    for (int nt = 0; nt < 8; ++nt) {
        int col = chalf + nt * 8 + tig * 2;
        float b1a = m1_b[col], b1b = m1_b[col + 1];
        __half* hb = hst + (col >> 5) * 2560 + (col & 31);
        *(__half2*)&hb[r0 * 40] =
            __floats2half2_rn(fmaxf(acc[nt*4+0] + b1a, 0.f), fmaxf(acc[nt*4+1] + b1b, 0.f));
        *(__half2*)&hb[(r0 + 8) * 40] =
            __floats2half2_rn(fmaxf(acc[nt*4+2] + b1a, 0.f), fmaxf(acc[nt*4+3] + b1b, 0.f));
    }
    #pragma unroll
    for (int i = 0; i < 32; ++i) acc[i] = 0.f;

    for (int t = 0; t < 4; ++t) {
        LOADB4(m2_w, 128, t * 32);
        __syncthreads();
        STSB4();
        __syncthreads();
        mma16_warp<8>(acc, hst + t * 2560 + rslab * 40, sbtm + chalf * 40, lane);
    }
    #pragma unroll
    for (int nt = 0; nt < 8; ++nt) {
        int col = chalf + nt * 8 + tig * 2;
        float b2a = m2_b[col], b2b = m2_b[col + 1];
        *(float2*)&y[(size_t)(b0 + r0) * 128 + col] =
            make_float2(acc[nt*4+0] + b2a, acc[nt*4+1] + b2b);
        *(float2*)&y[(size_t)(b0 + r0 + 8) * 128 + col] =
            make_float2(acc[nt*4+2] + b2a, acc[nt*4+3] + b2b);
    }
    #undef LOADB4
    #undef STSB4
    #undef LOADA_X
    #undef STSA_X
}

// ---------------- launch ----------------
extern "C" void kernel_launch(void* const* d_in, const int* in_sizes, int n_in,
                              void* d_out, int out_size) {
    const float* src    = (const float*)d_in[0];
    const float* seq    = (const float*)d_in[1];
    const float* seq_e  = (const float*)d_in[2];
    const float* src_ts = (const float*)d_in[3];
    const float* seq_ts = (const float*)d_in[4];
    const unsigned int* mask = (const unsigned int*)d_in[5];
    const float* freq   = (const float*)d_in[6];
    const float* phase  = (const float*)d_in[7];
    const float* Wq     = (const float*)d_in[8];
    const float* Wk     = (const float*)d_in[9];
    const float* Wv     = (const float*)d_in[10];
    const float* fc_w   = (const float*)d_in[11];
    const float* fc_b   = (const float*)d_in[12];
    const float* ln_g   = (const float*)d_in[13];
    const float* ln_b   = (const float*)d_in[14];
    const float* m1_w   = (const float*)d_in[15];
    const float* m1_b   = (const float*)d_in[16];
    const float* m2_w   = (const float*)d_in[17];
    const float* m2_b   = (const float*)d_in[18];

    float* y_out = (float*)d_out;
    float* attn_out = y_out + (size_t)BB * DD;

    k_te    <<<8192, 256>>>(src_ts, freq, phase);
    k_prepm <<<192, 256>>>(Wq, Wk);
    k_qt    <<<2048, 256>>>(src);
    k_attn  <<<BB, 256>>>(seq, seq_e, seq_ts, mask, freq, phase, attn_out);
    k_vout  <<<512, 256>>>(Wv);
    k_fc    <<<512, 256>>>(src, src_ts, freq, phase, fc_w, fc_b);
    k_mlp   <<<256, 256>>>(src, ln_g, ln_b, m1_w, m1_b, m2_w, m2_b, y_out);
}